// round 3
// baseline (speedup 1.0000x reference)
#include <cuda_runtime.h>
#include <cuda_bf16.h>
#include <math.h>

#define Bb 2
#define Nn 286
#define HH 150
#define TE 8            // edges per tile
#define MAXE 82944      // >= B*N*(N+1)/2 = 82082

// ---------------- device scratch (no allocations allowed) ----------------
__device__ int   g_edge_count;
__device__ int   g_packed[MAXE];  // (b<<20)|(i<<10)|j
__device__ float g_dist[MAXE];
__device__ float g_f0[Bb*Nn*4];
__device__ float g_f1[Bb*Nn*8];
__device__ float g_f2[Bb*Nn*8];
__device__ float g_f3[Bb*Nn*8];

__device__ __forceinline__ float sp_act(float x) {
    // softplus(5x)/5
    float t = 5.0f * x;
    if (t > 15.0f) return x;
    return 0.2f * __logf(1.0f + __expf(t));
}

// ---------------- init: zero accumulators, embed features ----------------
__global__ void init_kernel(const int* __restrict__ Z, const float* __restrict__ emb) {
    int t = blockIdx.x * blockDim.x + threadIdx.x;
    if (t == 0) g_edge_count = 0;
    if (t < Bb*Nn*8) { g_f1[t] = 0.f; g_f2[t] = 0.f; g_f3[t] = 0.f; }
    if (t < Bb*Nn*4) {
        int n = t >> 2, c = t & 3;
        g_f0[t] = emb[Z[n]*4 + c];
    }
}

// ---------------- build compacted unordered-pair list ----------------
__global__ void build_edges(const float* __restrict__ xyz) {
    int t = blockIdx.x * blockDim.x + threadIdx.x;
    if (t >= Bb*Nn*Nn) return;
    int b = t / (Nn*Nn);
    int r = t % (Nn*Nn);
    int i = r / Nn, j = r % Nn;
    if (j < i) return;                      // unordered pairs + self
    const float* pi = xyz + (b*Nn + i)*3;
    const float* pj = xyz + (b*Nn + j)*3;
    float dx = pi[0]-pj[0], dy = pi[1]-pj[1], dz = pi[2]-pj[2];
    float d = sqrtf(dx*dx + dy*dy + dz*dz + 1e-12f);
    if (d <= 3.0f) {
        int idx = atomicAdd(&g_edge_count, 1);
        g_packed[idx] = (b << 20) | (i << 10) | j;
        g_dist[idx]   = d;
    }
}

// ---------------- half of a 150x150 hidden layer (k-split) ----------------
// Computes partial dot over k in [kbeg, kbeg+75) for unit `ut` across 8 edges.
__device__ __forceinline__ void hidden_half(const float* __restrict__ src,
                                            float* __restrict__ pdst,
                                            const float* __restrict__ W,
                                            int ut, int kbeg) {
    if (ut >= HH) return;
    float acc[TE];
    #pragma unroll
    for (int e = 0; e < TE; e++) acc[e] = 0.f;
    const float* wc = W + ut;
    #pragma unroll 1
    for (int kk = kbeg; kk < kbeg + 75; kk += 5) {
        float w[5];
        #pragma unroll
        for (int u = 0; u < 5; u++) w[u] = __ldg(wc + (kk + u)*HH);
        #pragma unroll
        for (int u = 0; u < 5; u++) {
            const float4* hr = reinterpret_cast<const float4*>(src + (kk + u)*TE);
            float4 h0 = hr[0], h1 = hr[1];
            acc[0] = fmaf(h0.x, w[u], acc[0]);  acc[1] = fmaf(h0.y, w[u], acc[1]);
            acc[2] = fmaf(h0.z, w[u], acc[2]);  acc[3] = fmaf(h0.w, w[u], acc[3]);
            acc[4] = fmaf(h1.x, w[u], acc[4]);  acc[5] = fmaf(h1.y, w[u], acc[5]);
            acc[6] = fmaf(h1.z, w[u], acc[6]);  acc[7] = fmaf(h1.w, w[u], acc[7]);
        }
    }
    float4* dr = reinterpret_cast<float4*>(pdst + ut*TE);
    dr[0] = make_float4(acc[0], acc[1], acc[2], acc[3]);
    dr[1] = make_float4(acc[4], acc[5], acc[6], acc[7]);
}

// ---------------- fused conv: radial MLP per pair + scatter ----------------
template<int LAYER, int DIN, int DOUT>
__global__ __launch_bounds__(320)
void conv_kernel(const float* __restrict__ Wr1, const float* __restrict__ Wr2,
                 const float* __restrict__ Wr3, const float* __restrict__ Wro) {
    constexpr int DIO    = DIN * DOUT;      // 32 or 64
    constexpr int GROUPS = 256 / DIO;       // 8 or 4
    constexpr int EPG    = TE / GROUPS;     // 1 or 2

    const float* __restrict__ fin  = (LAYER == 0) ? g_f0 : (LAYER == 1 ? g_f1 : g_f2);
    float*       __restrict__ fout = (LAYER == 0) ? g_f1 : (LAYER == 1 ? g_f2 : g_f3);

    __shared__ __align__(16) float HA[HH*TE];   // activations
    __shared__ __align__(16) float HB[HH*TE];   // partial (half 0)
    __shared__ __align__(16) float HP[HH*TE];   // partial (half 1)
    __shared__ float WOUT[TE*64];
    __shared__ float sb0[TE], sb1[TE], sb2[TE];
    __shared__ float fI[TE][8], fJ[TE][8];
    __shared__ int   sPack[TE];

    const int tid  = threadIdx.x;
    const int ut   = tid % 160;             // hidden unit (active if <150)
    const int kbeg = (tid / 160) * 75;      // k-half: 0 or 75
    const int cnt = g_edge_count;
    const int ntiles = (cnt + TE - 1) / TE;
    const float scale = 1.0f / sqrtf(150.0f * (float)DIN);
    const float INV_SQRT150 = 0.0816496580927726f;
    const float INV_SQRT3 = 0.5773502691896258f;
    const float PI_2 = 1.5707963267948966f;

    for (int tile = blockIdx.x; tile < ntiles; tile += gridDim.x) {
        // stage edge metadata, basis, endpoint features
        if (tid < TE) {
            int idx = tile*TE + tid;
            if (idx < cnt) {
                int p = g_packed[idx];
                sPack[tid] = p;
                int b = p >> 20, i = (p >> 10) & 1023, j = p & 1023;
                float d  = g_dist[idx];
                float x0 = d * (1.0f/1.5f);
                float x1 = x0 - 1.0f;
                float x2 = x0 - 2.0f;
                float c0 = cosf(PI_2*x0), c1 = cosf(PI_2*x1), c2 = cosf(PI_2*x2);
                sb0[tid] = (fabsf(x0) < 1.f) ? c0*c0 : 0.f;
                sb1[tid] = (fabsf(x1) < 1.f) ? c1*c1 : 0.f;
                sb2[tid] = (fabsf(x2) < 1.f) ? c2*c2 : 0.f;
                #pragma unroll
                for (int c = 0; c < DIN; c++) {
                    fI[tid][c] = fin[(b*Nn + i)*DIN + c];
                    fJ[tid][c] = fin[(b*Nn + j)*DIN + c];
                }
            } else {
                sPack[tid] = -1;
                sb0[tid] = sb1[tid] = sb2[tid] = 0.f;
            }
        }
        __syncthreads();

        // layer 1: basis(3) -> 150
        if (tid < HH) {
            float wa = Wr1[tid]        * INV_SQRT3;
            float wb = Wr1[HH + tid]   * INV_SQRT3;
            float wc = Wr1[2*HH + tid] * INV_SQRT3;
            #pragma unroll
            for (int e = 0; e < TE; e++)
                HA[tid*TE + e] = sp_act(fmaf(sb0[e], wa, fmaf(sb1[e], wb, sb2[e]*wc)));
        }
        __syncthreads();

        // layer 2: k-split halves produce partials, then combine+activate
        hidden_half(HA, (kbeg == 0) ? HB : HP, Wr2, ut, kbeg);
        __syncthreads();
        if (tid < HH*TE/4) {
            float4 a = reinterpret_cast<const float4*>(HB)[tid];
            float4 b = reinterpret_cast<const float4*>(HP)[tid];
            float4 r;
            r.x = sp_act((a.x + b.x) * INV_SQRT150);
            r.y = sp_act((a.y + b.y) * INV_SQRT150);
            r.z = sp_act((a.z + b.z) * INV_SQRT150);
            r.w = sp_act((a.w + b.w) * INV_SQRT150);
            reinterpret_cast<float4*>(HA)[tid] = r;
        }
        __syncthreads();

        // layer 3: same pattern
        hidden_half(HA, (kbeg == 0) ? HB : HP, Wr3, ut, kbeg);
        __syncthreads();
        if (tid < HH*TE/4) {
            float4 a = reinterpret_cast<const float4*>(HB)[tid];
            float4 b = reinterpret_cast<const float4*>(HP)[tid];
            float4 r;
            r.x = sp_act((a.x + b.x) * INV_SQRT150);
            r.y = sp_act((a.y + b.y) * INV_SQRT150);
            r.z = sp_act((a.z + b.z) * INV_SQRT150);
            r.w = sp_act((a.w + b.w) * INV_SQRT150);
            reinterpret_cast<float4*>(HA)[tid] = r;
        }
        __syncthreads();

        // output layer: 150 -> DIO per edge (prefetched weight chunks)
        if (tid < DIO * GROUPS) {
            int o  = tid % DIO;
            int eg = tid / DIO;
            float acc[EPG];
            #pragma unroll
            for (int e = 0; e < EPG; e++) acc[e] = 0.f;
            const float* wc = Wro + o;
            #pragma unroll 1
            for (int kk = 0; kk < HH; kk += 6) {
                float w[6];
                #pragma unroll
                for (int u = 0; u < 6; u++) w[u] = __ldg(wc + (kk + u)*DIO);
                #pragma unroll
                for (int u = 0; u < 6; u++) {
                    const float* hr = HA + (kk + u)*TE + eg*EPG;
                    #pragma unroll
                    for (int e = 0; e < EPG; e++) acc[e] = fmaf(hr[e], w[u], acc[e]);
                }
            }
            #pragma unroll
            for (int e = 0; e < EPG; e++) WOUT[(eg*EPG + e)*64 + o] = acc[e];
        }
        __syncthreads();

        // K @ f scatter — both directions of the unordered pair
        if (tid < TE * DOUT) {
            int e = tid / DOUT, a = tid % DOUT;
            int p = sPack[e];
            if (p >= 0) {
                int b = p >> 20, i = (p >> 10) & 1023, j = p & 1023;
                float s1 = 0.f, s2 = 0.f;
                #pragma unroll
                for (int ji = 0; ji < DIN; ji++) {
                    float w = WOUT[e*64 + a*DIN + ji];
                    s1 = fmaf(w, fJ[e][ji], s1);
                    s2 = fmaf(w, fI[e][ji], s2);
                }
                atomicAdd(&fout[(b*Nn + i)*DOUT + a], s1 * scale);
                if (i != j) atomicAdd(&fout[(b*Nn + j)*DOUT + a], s2 * scale);
            }
        }
        __syncthreads();
    }
}

// ---------------- epilogue: lp-pool, linear, batchnorm, leaky relu ----------
__global__ void final_kernel(const float* __restrict__ lin_w, const float* __restrict__ lin_b,
                             const float* __restrict__ bn_g,  const float* __restrict__ bn_b,
                             float* __restrict__ out) {
    __shared__ float pooled[2][24];
    __shared__ float yv[2][24];
    int t = threadIdx.x;
    if (t < 48) {
        int b = t / 24, c = t % 24;
        const float* src; int cc;
        if      (c < 8)  { src = g_f1; cc = c;      }
        else if (c < 16) { src = g_f2; cc = c - 8;  }
        else             { src = g_f3; cc = c - 16; }
        float s = 0.f;
        for (int n = 0; n < Nn; n++) {
            float v = src[(b*Nn + n)*8 + cc];
            s = fmaf(v, v, s);
        }
        pooled[b][c] = sqrtf(s + 1e-12f);
    }
    __syncthreads();
    if (t < 48) {
        int b = t / 24, o = t % 24;
        float s = lin_b[o];
        for (int c = 0; c < 24; c++) s = fmaf(pooled[b][c], lin_w[o*24 + c], s);
        yv[b][o] = s;
    }
    __syncthreads();
    if (t < 24) {
        float y0 = yv[0][t], y1 = yv[1][t];
        float m   = 0.5f * (y0 + y1);
        float d0  = y0 - m, d1 = y1 - m;
        float var = 0.5f * (d0*d0 + d1*d1);
        float inv = 1.0f / sqrtf(var + 1e-5f);
        #pragma unroll
        for (int b = 0; b < 2; b++) {
            float v = (yv[b][t] - m) * inv * bn_g[t] + bn_b[t];
            out[b*24 + t] = (v > 0.f) ? v : 0.2f * v;
        }
    }
}

// ---------------- launch ----------------
extern "C" void kernel_launch(void* const* d_in, const int* in_sizes, int n_in,
                              void* d_out, int out_size) {
    const float* xyz   = (const float*)d_in[0];
    const int*   Z     = (const int*)  d_in[1];
    const float* emb   = (const float*)d_in[2];
    const float* c0w1  = (const float*)d_in[3];
    const float* c0w2  = (const float*)d_in[4];
    const float* c0w3  = (const float*)d_in[5];
    const float* c0wo  = (const float*)d_in[6];
    const float* c1w1  = (const float*)d_in[7];
    const float* c1w2  = (const float*)d_in[8];
    const float* c1w3  = (const float*)d_in[9];
    const float* c1wo  = (const float*)d_in[10];
    const float* c2w1  = (const float*)d_in[11];
    const float* c2w2  = (const float*)d_in[12];
    const float* c2w3  = (const float*)d_in[13];
    const float* c2wo  = (const float*)d_in[14];
    const float* lin_w = (const float*)d_in[15];
    const float* lin_b = (const float*)d_in[16];
    const float* bn_g  = (const float*)d_in[17];
    const float* bn_b  = (const float*)d_in[18];
    float* out = (float*)d_out;

    init_kernel<<<(Bb*Nn*8 + 255)/256, 256>>>(Z, emb);
    build_edges<<<(Bb*Nn*Nn + 255)/256, 256>>>(xyz);
    conv_kernel<0, 4, 8><<<1184, 320>>>(c0w1, c0w2, c0w3, c0wo);
    conv_kernel<1, 8, 8><<<1184, 320>>>(c1w1, c1w2, c1w3, c1wo);
    conv_kernel<2, 8, 8><<<1184, 320>>>(c2w1, c2w2, c2w3, c2wo);
    final_kernel<<<1, 64>>>(lin_w, lin_b, bn_g, bn_b, out);
}

// round 6
// speedup vs baseline: 1.2965x; 1.2965x over previous
#include <cuda_runtime.h>
#include <cuda_bf16.h>
#include <math.h>

#define Bb 2
#define Nn 286
#define HH 150
#define TE 8            // edges per tile
#define MAXE 82944      // >= B*N*(N+1)/2 = 82082

// ---------------- device scratch (no allocations allowed) ----------------
// NOTE: these symbols must ONLY be referenced from device code. Referencing
// them in host code binds the host shadow variable (silent corruption on
// GB300 because ATS makes host addresses GPU-dereferenceable).
__device__ int   g_edge_count;
__device__ int   g_packed[MAXE];  // (b<<20)|(i<<10)|j
__device__ float g_dist[MAXE];
__device__ float g_f0[Bb*Nn*4];
__device__ float g_f1[Bb*Nn*8];
__device__ float g_f2[Bb*Nn*8];
__device__ float g_f3[Bb*Nn*8];
// per-edge radial kernels (scratch; L2-resident at typical edge counts)
__device__ float g_K0[MAXE*32];
__device__ float g_K1[MAXE*64];
__device__ float g_K2[MAXE*64];

__device__ __forceinline__ float sp_act(float x) {
    // softplus(5x)/5
    float t = 5.0f * x;
    if (t > 15.0f) return x;
    return 0.2f * __logf(1.0f + __expf(t));
}

// ---------------- init: zero accumulators, embed features ----------------
__global__ void init_kernel(const int* __restrict__ Z, const float* __restrict__ emb) {
    int t = blockIdx.x * blockDim.x + threadIdx.x;
    if (t == 0) g_edge_count = 0;
    if (t < Bb*Nn*8) { g_f1[t] = 0.f; g_f2[t] = 0.f; g_f3[t] = 0.f; }
    if (t < Bb*Nn*4) {
        int n = t >> 2, c = t & 3;
        g_f0[t] = emb[Z[n]*4 + c];
    }
}

// ---------------- build compacted unordered-pair list ----------------
__global__ void build_edges(const float* __restrict__ xyz) {
    int t = blockIdx.x * blockDim.x + threadIdx.x;
    if (t >= Bb*Nn*Nn) return;
    int b = t / (Nn*Nn);
    int r = t % (Nn*Nn);
    int i = r / Nn, j = r % Nn;
    if (j < i) return;                      // unordered pairs + self
    const float* pi = xyz + (b*Nn + i)*3;
    const float* pj = xyz + (b*Nn + j)*3;
    float dx = pi[0]-pj[0], dy = pi[1]-pj[1], dz = pi[2]-pj[2];
    float d = sqrtf(dx*dx + dy*dy + dz*dz + 1e-12f);
    if (d <= 3.0f) {
        int idx = atomicAdd(&g_edge_count, 1);
        g_packed[idx] = (b << 20) | (i << 10) | j;
        g_dist[idx]   = d;
    }
}

// ---------------- hidden 150x150 layer over an 8-edge tile ----------------
__device__ __forceinline__ void hidden_layer(const float* __restrict__ src,
                                             float* __restrict__ dst,
                                             const float* __restrict__ W, int tid) {
    if (tid < HH) {
        float acc[TE];
        #pragma unroll
        for (int e = 0; e < TE; e++) acc[e] = 0.f;
        const float* wc = W + tid;
        #pragma unroll 1
        for (int kk = 0; kk < HH; kk += 6) {
            float w[6];
            #pragma unroll
            for (int u = 0; u < 6; u++) w[u] = __ldg(wc + (kk + u)*HH);
            #pragma unroll
            for (int u = 0; u < 6; u++) {
                const float4* hr = reinterpret_cast<const float4*>(src + (kk + u)*TE);
                float4 h0 = hr[0], h1 = hr[1];
                acc[0] = fmaf(h0.x, w[u], acc[0]);  acc[1] = fmaf(h0.y, w[u], acc[1]);
                acc[2] = fmaf(h0.z, w[u], acc[2]);  acc[3] = fmaf(h0.w, w[u], acc[3]);
                acc[4] = fmaf(h1.x, w[u], acc[4]);  acc[5] = fmaf(h1.y, w[u], acc[5]);
                acc[6] = fmaf(h1.z, w[u], acc[6]);  acc[7] = fmaf(h1.w, w[u], acc[7]);
            }
        }
        const float S = 0.0816496580927726f;   // 1/sqrt(150)
        float4 o0, o1;
        o0.x = sp_act(acc[0]*S); o0.y = sp_act(acc[1]*S);
        o0.z = sp_act(acc[2]*S); o0.w = sp_act(acc[3]*S);
        o1.x = sp_act(acc[4]*S); o1.y = sp_act(acc[5]*S);
        o1.z = sp_act(acc[6]*S); o1.w = sp_act(acc[7]*S);
        float4* dr = reinterpret_cast<float4*>(dst + tid*TE);
        dr[0] = o0; dr[1] = o1;
    }
}

// ---------------- output layer: 150 -> DIO per edge ------------------------
template<int DIO>
__device__ __forceinline__ void out_layer(const float* __restrict__ HA,
                                          const float* __restrict__ wo,
                                          float* __restrict__ Kout, int tid) {
    constexpr int GROUPS = 128 / DIO;       // 4 (DIO=32) or 2 (DIO=64)
    constexpr int EPG    = TE / GROUPS;     // 2 or 4
    if (tid >= 128) return;
    int o  = tid % DIO;
    int eg = tid / DIO;
    float acc[EPG];
    #pragma unroll
    for (int e = 0; e < EPG; e++) acc[e] = 0.f;
    const float* wc = wo + o;
    #pragma unroll 1
    for (int kk = 0; kk < HH; kk += 6) {
        float w[6];
        #pragma unroll
        for (int u = 0; u < 6; u++) w[u] = __ldg(wc + (kk + u)*DIO);
        #pragma unroll
        for (int u = 0; u < 6; u++) {
            const float* hr = HA + (kk + u)*TE + eg*EPG;
            #pragma unroll
            for (int e = 0; e < EPG; e++) acc[e] = fmaf(hr[e], w[u], acc[e]);
        }
    }
    #pragma unroll
    for (int e = 0; e < EPG; e++) Kout[(eg*EPG + e)*DIO + o] = acc[e];
}

// ---------------- radial MLP for all 3 convs (independent work items) ------
__global__ __launch_bounds__(160)
void radial_kernel(const float* __restrict__ c0w1, const float* __restrict__ c0w2,
                   const float* __restrict__ c0w3, const float* __restrict__ c0wo,
                   const float* __restrict__ c1w1, const float* __restrict__ c1w2,
                   const float* __restrict__ c1w3, const float* __restrict__ c1wo,
                   const float* __restrict__ c2w1, const float* __restrict__ c2w2,
                   const float* __restrict__ c2w3, const float* __restrict__ c2wo) {
    __shared__ __align__(16) float HA[HH*TE];
    __shared__ __align__(16) float HB[HH*TE];
    __shared__ float sb0[TE], sb1[TE], sb2[TE];

    const int tid = threadIdx.x;
    const int cnt = g_edge_count;
    const int ntiles = (cnt + TE - 1) / TE;
    const int total = 3 * ntiles;
    const float INV_SQRT3 = 0.5773502691896258f;
    const float PI_2 = 1.5707963267948966f;

    for (int work = blockIdx.x; work < total; work += gridDim.x) {
        int layer = work % 3;
        int tile  = work / 3;
        const float *w1, *w2, *w3, *wo;
        if (layer == 0)      { w1 = c0w1; w2 = c0w2; w3 = c0w3; wo = c0wo; }
        else if (layer == 1) { w1 = c1w1; w2 = c1w2; w3 = c1w3; wo = c1wo; }
        else                 { w1 = c2w1; w2 = c2w2; w3 = c2w3; wo = c2wo; }

        // stage basis
        if (tid < TE) {
            int idx = tile*TE + tid;
            float d = (idx < cnt) ? g_dist[idx] : 1e9f;
            float x0 = d * (1.0f/1.5f);
            float x1 = x0 - 1.0f;
            float x2 = x0 - 2.0f;
            float c0 = cosf(PI_2*x0), c1 = cosf(PI_2*x1), c2 = cosf(PI_2*x2);
            sb0[tid] = (fabsf(x0) < 1.f) ? c0*c0 : 0.f;
            sb1[tid] = (fabsf(x1) < 1.f) ? c1*c1 : 0.f;
            sb2[tid] = (fabsf(x2) < 1.f) ? c2*c2 : 0.f;
        }
        __syncthreads();

        // layer 1: basis(3) -> 150
        if (tid < HH) {
            float wa = w1[tid]        * INV_SQRT3;
            float wb = w1[HH + tid]   * INV_SQRT3;
            float wc = w1[2*HH + tid] * INV_SQRT3;
            #pragma unroll
            for (int e = 0; e < TE; e++)
                HA[tid*TE + e] = sp_act(fmaf(sb0[e], wa, fmaf(sb1[e], wb, sb2[e]*wc)));
        }
        __syncthreads();
        hidden_layer(HA, HB, w2, tid);
        __syncthreads();
        hidden_layer(HB, HA, w3, tid);
        __syncthreads();

        if (layer == 0)      out_layer<32>(HA, wo, g_K0 + tile*TE*32, tid);
        else if (layer == 1) out_layer<64>(HA, wo, g_K1 + tile*TE*64, tid);
        else                 out_layer<64>(HA, wo, g_K2 + tile*TE*64, tid);
        __syncthreads();
    }
}

// ---------------- scatter: out[b,i] += K(e) @ f[b,j] (both directions) -----
// LAYER selects the g_* arrays INSIDE device code (host must not touch them).
template<int LAYER>
__global__ void scatter_kernel() {
    constexpr int DIN  = (LAYER == 0) ? 4 : 8;
    constexpr int DOUT = 8;
    const float* __restrict__ K   = (LAYER == 0) ? g_K0 : (LAYER == 1 ? g_K1 : g_K2);
    const float* __restrict__ fin = (LAYER == 0) ? g_f0 : (LAYER == 1 ? g_f1 : g_f2);
    float*       __restrict__ fout= (LAYER == 0) ? g_f1 : (LAYER == 1 ? g_f2 : g_f3);

    const int cnt = g_edge_count;
    const int total = cnt * DOUT;
    const float scale = rsqrtf(150.0f * (float)DIN);
    for (int t = blockIdx.x*blockDim.x + threadIdx.x; t < total;
         t += gridDim.x*blockDim.x) {
        int e = t / DOUT, a = t % DOUT;
        int p = g_packed[e];
        int b = p >> 20, i = (p >> 10) & 1023, j = p & 1023;
        const float* krow = K + e*(DIN*DOUT) + a*DIN;
        const float* fj = fin + (b*Nn + j)*DIN;
        const float* fi = fin + (b*Nn + i)*DIN;
        float s1 = 0.f, s2 = 0.f;
        #pragma unroll
        for (int ji = 0; ji < DIN; ji++) {
            float w = krow[ji];
            s1 = fmaf(w, fj[ji], s1);
            s2 = fmaf(w, fi[ji], s2);
        }
        atomicAdd(&fout[(b*Nn + i)*DOUT + a], s1 * scale);
        if (i != j) atomicAdd(&fout[(b*Nn + j)*DOUT + a], s2 * scale);
    }
}

// ---------------- epilogue: lp-pool, linear, batchnorm, leaky relu ----------
__global__ void final_kernel(const float* __restrict__ lin_w, const float* __restrict__ lin_b,
                             const float* __restrict__ bn_g,  const float* __restrict__ bn_b,
                             float* __restrict__ out) {
    __shared__ float pooled[2][24];
    __shared__ float yv[2][24];
    int t = threadIdx.x;
    if (t < 48) {
        int b = t / 24, c = t % 24;
        const float* src; int cc;
        if      (c < 8)  { src = g_f1; cc = c;      }
        else if (c < 16) { src = g_f2; cc = c - 8;  }
        else             { src = g_f3; cc = c - 16; }
        float s = 0.f;
        for (int n = 0; n < Nn; n++) {
            float v = src[(b*Nn + n)*8 + cc];
            s = fmaf(v, v, s);
        }
        pooled[b][c] = sqrtf(s + 1e-12f);
    }
    __syncthreads();
    if (t < 48) {
        int b = t / 24, o = t % 24;
        float s = lin_b[o];
        for (int c = 0; c < 24; c++) s = fmaf(pooled[b][c], lin_w[o*24 + c], s);
        yv[b][o] = s;
    }
    __syncthreads();
    if (t < 24) {
        float y0 = yv[0][t], y1 = yv[1][t];
        float m   = 0.5f * (y0 + y1);
        float d0  = y0 - m, d1 = y1 - m;
        float var = 0.5f * (d0*d0 + d1*d1);
        float inv = 1.0f / sqrtf(var + 1e-5f);
        #pragma unroll
        for (int b = 0; b < 2; b++) {
            float v = (yv[b][t] - m) * inv * bn_g[t] + bn_b[t];
            out[b*24 + t] = (v > 0.f) ? v : 0.2f * v;
        }
    }
}

// ---------------- launch ----------------
extern "C" void kernel_launch(void* const* d_in, const int* in_sizes, int n_in,
                              void* d_out, int out_size) {
    const float* xyz   = (const float*)d_in[0];
    const int*   Z     = (const int*)  d_in[1];
    const float* emb   = (const float*)d_in[2];
    const float* c0w1  = (const float*)d_in[3];
    const float* c0w2  = (const float*)d_in[4];
    const float* c0w3  = (const float*)d_in[5];
    const float* c0wo  = (const float*)d_in[6];
    const float* c1w1  = (const float*)d_in[7];
    const float* c1w2  = (const float*)d_in[8];
    const float* c1w3  = (const float*)d_in[9];
    const float* c1wo  = (const float*)d_in[10];
    const float* c2w1  = (const float*)d_in[11];
    const float* c2w2  = (const float*)d_in[12];
    const float* c2w3  = (const float*)d_in[13];
    const float* c2wo  = (const float*)d_in[14];
    const float* lin_w = (const float*)d_in[15];
    const float* lin_b = (const float*)d_in[16];
    const float* bn_g  = (const float*)d_in[17];
    const float* bn_b  = (const float*)d_in[18];
    float* out = (float*)d_out;

    init_kernel<<<(Bb*Nn*8 + 255)/256, 256>>>(Z, emb);
    build_edges<<<(Bb*Nn*Nn + 255)/256, 256>>>(xyz);
    radial_kernel<<<2664, 160>>>(c0w1, c0w2, c0w3, c0wo,
                                 c1w1, c1w2, c1w3, c1wo,
                                 c2w1, c2w2, c2w3, c2wo);
    scatter_kernel<0><<<296, 256>>>();
    scatter_kernel<1><<<296, 256>>>();
    scatter_kernel<2><<<296, 256>>>();
    final_kernel<<<1, 64>>>(lin_w, lin_b, bn_g, bn_b, out);
}